// round 12
// baseline (speedup 1.0000x reference)
#include <cuda_runtime.h>
#include <cuda_bf16.h>
#include <stdint.h>
#include <math.h>

#define N_NODES 50000
#define N_EDGES 800000
#define D_MODEL 256
#define HEADS   8
#define D_K     32
#define QKV     256
#define NTOT    768   // q|k|v concatenated

// ---------------- scratch ----------------
__device__ float g_q[N_NODES * QKV];
__device__ float g_kv[N_NODES * 2 * QKV];   // [node][0:256)=k, [256:512)=v (interleaved)
__device__ __nv_bfloat16 g_xhi[N_NODES * D_MODEL];
__device__ __nv_bfloat16 g_xlo[N_NODES * D_MODEL];
__device__ __nv_bfloat16 g_wthi[NTOT * D_MODEL];   // W^T rows: n in [0,768), k in [0,256)
__device__ __nv_bfloat16 g_wtlo[NTOT * D_MODEL];
__device__ int g_deg[N_NODES];
__device__ int g_off[N_NODES + 1];
__device__ int g_cur[N_NODES];
__device__ int g_srcs[N_EDGES];
#define N_SBLK ((N_NODES + 255) / 256)
__device__ int g_bsum[N_SBLK];

// ---------------- PTX helpers (plain sm_100-legal) ----------------
__device__ __forceinline__ uint32_t smem_u32(const void* p) {
    uint32_t a;
    asm("{ .reg .u64 t; cvta.to.shared.u64 t, %1; cvt.u32.u64 %0, t; }" : "=r"(a) : "l"(p));
    return a;
}
__device__ __forceinline__ void cp_async16(uint32_t daddr, const void* gptr) {
    asm volatile("cp.async.cg.shared.global [%0], [%1], 16;" :: "r"(daddr), "l"(gptr) : "memory");
}
#define CP_COMMIT() asm volatile("cp.async.commit_group;" ::: "memory")
#define CP_WAIT(n)  asm volatile("cp.async.wait_group %0;" :: "n"(n) : "memory")

__device__ __forceinline__ void ldmatrix_x4(uint32_t& a0, uint32_t& a1, uint32_t& a2, uint32_t& a3, uint32_t addr) {
    asm volatile("ldmatrix.sync.aligned.m8n8.x4.shared.b16 {%0,%1,%2,%3}, [%4];"
                 : "=r"(a0), "=r"(a1), "=r"(a2), "=r"(a3) : "r"(addr));
}
__device__ __forceinline__ void ldmatrix_x2(uint32_t& b0, uint32_t& b1, uint32_t addr) {
    asm volatile("ldmatrix.sync.aligned.m8n8.x2.shared.b16 {%0,%1}, [%2];"
                 : "=r"(b0), "=r"(b1) : "r"(addr));
}
__device__ __forceinline__ void mma_bf16(float* d, const uint32_t* a, const uint32_t* b) {
    asm volatile(
        "mma.sync.aligned.m16n8k16.row.col.f32.bf16.bf16.f32 "
        "{%0,%1,%2,%3}, {%4,%5,%6,%7}, {%8,%9}, {%0,%1,%2,%3};"
        : "+f"(d[0]), "+f"(d[1]), "+f"(d[2]), "+f"(d[3])
        : "r"(a[0]), "r"(a[1]), "r"(a[2]), "r"(a[3]), "r"(b[0]), "r"(b[1]));
}

// =============== bf16 split conversion ===============
__global__ void conv_x_kernel(const float* __restrict__ x) {
    int i = blockIdx.x * blockDim.x + threadIdx.x;   // float4 index
    if (i >= N_NODES * D_MODEL / 4) return;
    float4 f = *reinterpret_cast<const float4*>(x + i * 4);
    __nv_bfloat16 h[4], l[4];
    float vv[4] = {f.x, f.y, f.z, f.w};
    #pragma unroll
    for (int j = 0; j < 4; j++) {
        h[j] = __float2bfloat16_rn(vv[j]);
        l[j] = __float2bfloat16_rn(vv[j] - __bfloat162float(h[j]));
    }
    *reinterpret_cast<uint2*>(&g_xhi[i * 4]) = *reinterpret_cast<uint2*>(h);
    *reinterpret_cast<uint2*>(&g_xlo[i * 4]) = *reinterpret_cast<uint2*>(l);
}

__global__ void conv_w_kernel(const float* __restrict__ Wq,
                              const float* __restrict__ Wk,
                              const float* __restrict__ Wv) {
    int id = blockIdx.x * blockDim.x + threadIdx.x;  // 3*65536
    if (id >= NTOT * D_MODEL) return;
    int p = id >> 16;          // proj
    int r = id & 65535;
    int k = r & 255;
    int n = r >> 8;
    const float* W = (p == 0) ? Wq : (p == 1) ? Wk : Wv;
    float v = W[k * QKV + n];
    __nv_bfloat16 h = __float2bfloat16_rn(v);
    __nv_bfloat16 l = __float2bfloat16_rn(v - __bfloat162float(h));
    g_wthi[id] = h;
    g_wtlo[id] = l;
}

// =============== mma.sync bf16 GEMM: C[50000,768] = X[50000,256] @ W[256,768] ===============
// 3 split terms folded into K loop (K_eff = 768): term0 hi*hi, term1 lo*hi, term2 hi*lo.
// CTA tile 128x128, warp tile 64x32, BK=64, 3-stage cp.async pipeline (2
// iterations of prefetch slack; measured: 2-stage left ~35% tensor idle on
// CP_WAIT latency). __launch_bounds__(256,2): 2 CTAs/SM (127 regs measured).
#define GEMM_STAGE_BYTES 32768          // A 16KB + B 16KB
#define GEMM_STAGES 3
#define GEMM_SMEM (GEMM_STAGES * GEMM_STAGE_BYTES)   // 96 KB; x2 CTA = 192 KB < 228 KB

__device__ __forceinline__ void gemm_load_stage(uint32_t sbase, int s, int it,
                                                int tileM, int nbase, int tid) {
    const int term = it >> 2;
    const int k0   = (it & 3) * 64;
    const __nv_bfloat16* __restrict__ As = (term == 1) ? g_xlo : g_xhi;
    const __nv_bfloat16* __restrict__ Bs = (term == 2) ? g_wtlo : g_wthi;
    uint32_t aBase = sbase + s * GEMM_STAGE_BYTES;
    uint32_t bBase = aBase + 16384;
    #pragma unroll
    for (int i = 0; i < 4; i++) {
        int idx = tid + i * 256;          // 0..1023
        int row = idx >> 3;
        int c   = idx & 7;
        uint32_t soff = (uint32_t)row * 128u + (uint32_t)((c ^ (row & 7)) << 4);
        int grow = tileM + row;
        if (grow >= N_NODES) grow = 0;    // garbage only pollutes invalid output rows
        cp_async16(aBase + soff, As + (size_t)grow * D_MODEL + k0 + c * 8);
        int nrow = nbase + row;
        cp_async16(bBase + soff, Bs + (size_t)nrow * D_MODEL + k0 + c * 8);
    }
}

__global__ __launch_bounds__(256, 2) void gemm_mma(void) {
    extern __shared__ char smem[];
    const uint32_t sbase = smem_u32(smem);
    const int tid  = threadIdx.x;
    const int lane = tid & 31;
    const int wid  = tid >> 5;
    const int tileM = blockIdx.x * 128;
    const int nbase = blockIdx.y * 128;
    const int wm = wid & 1;      // m sub-tile (64)
    const int wn = wid >> 1;     // n sub-tile (32)

    // hoisted ldmatrix address components
    uint32_t aRowOff[4], bRowOff[4];
    int aR7, bR7;
    {
        int arow = wm * 64 + (lane & 15);
        aR7 = arow & 7;
        #pragma unroll
        for (int mi = 0; mi < 4; mi++)
            aRowOff[mi] = (uint32_t)(arow + mi * 16) * 128u;
        int l16 = lane & 15;
        int brow = wn * 32 + (l16 & 7);
        bR7 = brow & 7;
        #pragma unroll
        for (int ni = 0; ni < 4; ni++)
            bRowOff[ni] = (uint32_t)(brow + ni * 8) * 128u;
    }
    const int aCsel = (lane >> 4);        // 0/1
    const int bCsel = ((lane & 15) >> 3); // 0/1

    float acc[4][4][4];
    #pragma unroll
    for (int mi = 0; mi < 4; mi++)
        #pragma unroll
        for (int ni = 0; ni < 4; ni++)
            #pragma unroll
            for (int r = 0; r < 4; r++) acc[mi][ni][r] = 0.f;

    gemm_load_stage(sbase, 0, 0, tileM, nbase, tid);
    CP_COMMIT();
    gemm_load_stage(sbase, 1, 1, tileM, nbase, tid);
    CP_COMMIT();

    int s = 0;
    for (int it = 0; it < 12; ++it) {
        if (it + 2 < 12) {
            int ld = s + 2; if (ld >= GEMM_STAGES) ld -= GEMM_STAGES;
            gemm_load_stage(sbase, ld, it + 2, tileM, nbase, tid);
            CP_COMMIT();
            CP_WAIT(2);             // stage s (issued 2 iterations ago) complete
        } else if (it + 1 < 12) {
            CP_WAIT(1);
        } else {
            CP_WAIT(0);
        }
        __syncthreads();

        uint32_t aBase = sbase + (uint32_t)s * GEMM_STAGE_BYTES;
        uint32_t bBase = aBase + 16384;
        #pragma unroll
        for (int k16 = 0; k16 < 4; k16++) {
            uint32_t a[4][4];
            #pragma unroll
            for (int mi = 0; mi < 4; mi++) {
                int cc = k16 * 2 + aCsel;
                uint32_t addr = aBase + aRowOff[mi] + (uint32_t)((cc ^ aR7) << 4);
                ldmatrix_x4(a[mi][0], a[mi][1], a[mi][2], a[mi][3], addr);
            }
            uint32_t b[4][2];
            #pragma unroll
            for (int ni = 0; ni < 4; ni++) {
                int cc = k16 * 2 + bCsel;
                uint32_t addr = bBase + bRowOff[ni] + (uint32_t)((cc ^ bR7) << 4);
                ldmatrix_x2(b[ni][0], b[ni][1], addr);
            }
            #pragma unroll
            for (int mi = 0; mi < 4; mi++)
                #pragma unroll
                for (int ni = 0; ni < 4; ni++)
                    mma_bf16(acc[mi][ni], a[mi], b[ni]);
        }
        if (++s >= GEMM_STAGES) s = 0;
        __syncthreads();            // guard stage overwrite by next iteration's load
    }

    // epilogue: q -> g_q[m][col]; k -> g_kv[m][col]; v -> g_kv[m][256+col]
    #pragma unroll
    for (int mi = 0; mi < 4; mi++) {
        #pragma unroll
        for (int ni = 0; ni < 4; ni++) {
            int m0 = tileM + wm * 64 + mi * 16 + (lane >> 2);
            int ng = nbase + wn * 32 + ni * 8 + (lane & 3) * 2;
            int proj = ng >> 8;
            int col  = ng & 255;
            if (m0 < N_NODES) {
                float* dstp = (proj == 0)
                    ? g_q  + (size_t)m0 * QKV + col
                    : g_kv + (size_t)m0 * 512 + (proj == 2 ? 256 : 0) + col;
                *reinterpret_cast<float2*>(dstp) = make_float2(acc[mi][ni][0], acc[mi][ni][1]);
            }
            if (m0 + 8 < N_NODES) {
                float* dstp = (proj == 0)
                    ? g_q  + (size_t)(m0 + 8) * QKV + col
                    : g_kv + (size_t)(m0 + 8) * 512 + (proj == 2 ? 256 : 0) + col;
                *reinterpret_cast<float2*>(dstp) = make_float2(acc[mi][ni][2], acc[mi][ni][3]);
            }
        }
    }
}

// =============== edge binning ===============
__global__ void zero_deg_kernel() {
    int i = blockIdx.x * blockDim.x + threadIdx.x;
    if (i < N_NODES) g_deg[i] = 0;
}
__global__ void hist_kernel(const int* __restrict__ dst) {
    int i = blockIdx.x * blockDim.x + threadIdx.x;
    if (i < N_EDGES) atomicAdd(&g_deg[dst[i]], 1);
}
__global__ __launch_bounds__(256) void scan_partial() {
    __shared__ int sh[256];
    int tid = threadIdx.x;
    int i = blockIdx.x * 256 + tid;
    int v = (i < N_NODES) ? g_deg[i] : 0;
    sh[tid] = v;
    __syncthreads();
    #pragma unroll
    for (int o = 1; o < 256; o <<= 1) {
        int t = (tid >= o) ? sh[tid - o] : 0;
        __syncthreads();
        sh[tid] += t;
        __syncthreads();
    }
    if (i < N_NODES) g_off[i] = sh[tid] - v;     // exclusive within block
    if (tid == 255) g_bsum[blockIdx.x] = sh[255];
}
__global__ __launch_bounds__(256) void scan_bsums() {
    __shared__ int sh[256];
    int tid = threadIdx.x;
    int v = (tid < N_SBLK) ? g_bsum[tid] : 0;
    sh[tid] = v;
    __syncthreads();
    #pragma unroll
    for (int o = 1; o < 256; o <<= 1) {
        int t = (tid >= o) ? sh[tid - o] : 0;
        __syncthreads();
        sh[tid] += t;
        __syncthreads();
    }
    if (tid < N_SBLK) g_bsum[tid] = sh[tid] - v;  // exclusive block offsets
    if (tid == 0) g_off[N_NODES] = N_EDGES;
}
__global__ void scan_add() {
    int i = blockIdx.x * 256 + threadIdx.x;
    if (i < N_NODES) {
        int t = g_off[i] + g_bsum[blockIdx.x];
        g_off[i] = t;
        g_cur[i] = t;
    }
}
__global__ void scatter_kernel(const int* __restrict__ src, const int* __restrict__ dst) {
    int i = blockIdx.x * blockDim.x + threadIdx.x;
    if (i < N_EDGES) {
        int p = atomicAdd(&g_cur[dst[i]], 1);
        g_srcs[p] = src[i];
    }
}

// =============== per-node attention (warp per node, contiguous-lane layout) ===============
__global__ __launch_bounds__(256) void node_attn_kernel(float* __restrict__ out) {
    const int warp = (blockIdx.x * blockDim.x + threadIdx.x) >> 5;
    const int lane = threadIdx.x & 31;
    if (warp >= N_NODES) return;
    const int n = warp;
    const int beg = g_off[n];
    const int end = g_off[n + 1];

    const float* qp = g_q + (size_t)n * QKV + lane * 8;
    const float4 q0 = *reinterpret_cast<const float4*>(qp);
    const float4 q1 = *reinterpret_cast<const float4*>(qp + 4);

    float a0 = 0.f, a1 = 0.f, a2 = 0.f, a3 = 0.f;
    float a4 = 0.f, a5 = 0.f, a6 = 0.f, a7 = 0.f;
    float z = 0.f;

    const float isd = 0.17677669529663687f;  // 1/sqrt(32)
    const unsigned FULL = 0xffffffffu;

    if (beg < end) {
        const float* kp = g_kv + (size_t)g_srcs[beg] * 512 + lane * 8;
        float4 k0 = *reinterpret_cast<const float4*>(kp);
        float4 k1 = *reinterpret_cast<const float4*>(kp + 4);
        float4 v0 = *reinterpret_cast<const float4*>(kp + 256);
        float4 v1 = *reinterpret_cast<const float4*>(kp + 260);

        for (int i = beg; i < end; i++) {
            int nidx = i + 1 < end ? i + 1 : i;       // clamped prefetch index
            const float* np = g_kv + (size_t)g_srcs[nidx] * 512 + lane * 8;
            float4 nk0 = *reinterpret_cast<const float4*>(np);
            float4 nk1 = *reinterpret_cast<const float4*>(np + 4);
            float4 nv0 = *reinterpret_cast<const float4*>(np + 256);
            float4 nv1 = *reinterpret_cast<const float4*>(np + 260);

            float p = k0.x * q0.x;
            p = fmaf(k0.y, q0.y, p);
            p = fmaf(k0.z, q0.z, p);
            p = fmaf(k0.w, q0.w, p);
            p = fmaf(k1.x, q1.x, p);
            p = fmaf(k1.y, q1.y, p);
            p = fmaf(k1.z, q1.z, p);
            p = fmaf(k1.w, q1.w, p);
            p += __shfl_xor_sync(FULL, p, 1);
            p += __shfl_xor_sync(FULL, p, 2);
            // p = full head dot, replicated on the head's 4 lanes

            float e = __expf(fminf(fmaxf(p * isd, -5.f), 5.f));
            z += e;
            a0 = fmaf(v0.x, e, a0);
            a1 = fmaf(v0.y, e, a1);
            a2 = fmaf(v0.z, e, a2);
            a3 = fmaf(v0.w, e, a3);
            a4 = fmaf(v1.x, e, a4);
            a5 = fmaf(v1.y, e, a5);
            a6 = fmaf(v1.z, e, a6);
            a7 = fmaf(v1.w, e, a7);

            k0 = nk0; k1 = nk1; v0 = nv0; v1 = nv1;
        }
    }

    const float rz = 1.f / (z + 1e-9f);
    float* op = out + (size_t)n * QKV + lane * 8;
    *reinterpret_cast<float4*>(op)     = make_float4(a0 * rz, a1 * rz, a2 * rz, a3 * rz);
    *reinterpret_cast<float4*>(op + 4) = make_float4(a4 * rz, a5 * rz, a6 * rz, a7 * rz);
}

// =============== launch ===============
// Single stream, kernel launches + one cudaFuncSetAttribute ONLY (the host-API
// budget every passing round respected). gemm_mma at launch index 3 (ncu slot).
extern "C" void kernel_launch(void* const* d_in, const int* in_sizes, int n_in,
                              void* d_out, int out_size) {
    const float* x   = (const float*)d_in[0];
    const float* Wq  = (const float*)d_in[1];
    const float* Wk  = (const float*)d_in[2];
    const float* Wv  = (const float*)d_in[3];
    const int*   src = (const int*)d_in[4];
    const int*   dst = (const int*)d_in[5];
    float* out = (float*)d_out;

    cudaFuncSetAttribute(gemm_mma, cudaFuncAttributeMaxDynamicSharedMemorySize, GEMM_SMEM);

    // 0: bf16 split of x
    conv_x_kernel<<<(N_NODES * D_MODEL / 4 + 255) / 256, 256>>>(x);
    // 1: bf16 split of W
    conv_w_kernel<<<(NTOT * D_MODEL + 255) / 256, 256>>>(Wq, Wk, Wv);
    // 2: zero degree array
    zero_deg_kernel<<<(N_NODES + 255) / 256, 256>>>();
    // 3: fused QKV GEMM on tensor cores  <-- profiled launch
    dim3 ggrid((N_NODES + 127) / 128, NTOT / 128);
    gemm_mma<<<ggrid, 256, GEMM_SMEM>>>();
    // 4-8: edge binning (counting sort by dst)
    hist_kernel<<<(N_EDGES + 255) / 256, 256>>>(dst);
    scan_partial<<<N_SBLK, 256>>>();
    scan_bsums<<<1, 256>>>();
    scan_add<<<N_SBLK, 256>>>();
    scatter_kernel<<<(N_EDGES + 255) / 256, 256>>>(src, dst);
    // 9: per-node attention + normalization
    node_attn_kernel<<<(N_NODES * 32 + 255) / 256, 256>>>(out);
}

// round 13
// speedup vs baseline: 1.0062x; 1.0062x over previous
#include <cuda_runtime.h>
#include <cuda_bf16.h>
#include <stdint.h>
#include <math.h>

#define N_NODES 50000
#define N_EDGES 800000
#define D_MODEL 256
#define HEADS   8
#define D_K     32
#define QKV     256
#define NTOT    768   // q|k|v concatenated

// ---------------- scratch ----------------
__device__ float g_q[N_NODES * QKV];
__device__ float g_kv[N_NODES * 2 * QKV];   // [node][0:256)=k, [256:512)=v (interleaved)
__device__ __nv_bfloat16 g_xhi[N_NODES * D_MODEL];
__device__ __nv_bfloat16 g_xlo[N_NODES * D_MODEL];
__device__ __nv_bfloat16 g_wthi[NTOT * D_MODEL];   // W^T rows: n in [0,768), k in [0,256)
__device__ __nv_bfloat16 g_wtlo[NTOT * D_MODEL];
__device__ int g_deg[N_NODES];
__device__ int g_off[N_NODES + 1];
__device__ int g_cur[N_NODES];
__device__ int g_srcs[N_EDGES];
#define N_SBLK ((N_NODES + 255) / 256)
__device__ int g_bsum[N_SBLK];

// ---------------- PTX helpers (plain sm_100-legal) ----------------
__device__ __forceinline__ uint32_t smem_u32(const void* p) {
    uint32_t a;
    asm("{ .reg .u64 t; cvta.to.shared.u64 t, %1; cvt.u32.u64 %0, t; }" : "=r"(a) : "l"(p));
    return a;
}
__device__ __forceinline__ void cp_async16(uint32_t daddr, const void* gptr) {
    asm volatile("cp.async.cg.shared.global [%0], [%1], 16;" :: "r"(daddr), "l"(gptr) : "memory");
}
#define CP_COMMIT() asm volatile("cp.async.commit_group;" ::: "memory")
#define CP_WAIT(n)  asm volatile("cp.async.wait_group %0;" :: "n"(n) : "memory")

__device__ __forceinline__ void ldmatrix_x4(uint32_t& a0, uint32_t& a1, uint32_t& a2, uint32_t& a3, uint32_t addr) {
    asm volatile("ldmatrix.sync.aligned.m8n8.x4.shared.b16 {%0,%1,%2,%3}, [%4];"
                 : "=r"(a0), "=r"(a1), "=r"(a2), "=r"(a3) : "r"(addr));
}
__device__ __forceinline__ void ldmatrix_x2(uint32_t& b0, uint32_t& b1, uint32_t addr) {
    asm volatile("ldmatrix.sync.aligned.m8n8.x2.shared.b16 {%0,%1}, [%2];"
                 : "=r"(b0), "=r"(b1) : "r"(addr));
}
__device__ __forceinline__ void mma_bf16(float* d, const uint32_t* a, const uint32_t* b) {
    asm volatile(
        "mma.sync.aligned.m16n8k16.row.col.f32.bf16.bf16.f32 "
        "{%0,%1,%2,%3}, {%4,%5,%6,%7}, {%8,%9}, {%0,%1,%2,%3};"
        : "+f"(d[0]), "+f"(d[1]), "+f"(d[2]), "+f"(d[3])
        : "r"(a[0]), "r"(a[1]), "r"(a[2]), "r"(a[3]), "r"(b[0]), "r"(b[1]));
}

// =============== bf16 split conversion (+ fused binning pre-work, proven in R6) ===============
__global__ void conv_x_kernel(const float* __restrict__ x) {
    int i = blockIdx.x * blockDim.x + threadIdx.x;   // float4 index
    if (i < N_NODES) g_deg[i] = 0;                    // fused zero of degree array
    if (i >= N_NODES * D_MODEL / 4) return;
    float4 f = *reinterpret_cast<const float4*>(x + i * 4);
    __nv_bfloat16 h[4], l[4];
    float vv[4] = {f.x, f.y, f.z, f.w};
    #pragma unroll
    for (int j = 0; j < 4; j++) {
        h[j] = __float2bfloat16_rn(vv[j]);
        l[j] = __float2bfloat16_rn(vv[j] - __bfloat162float(h[j]));
    }
    *reinterpret_cast<uint2*>(&g_xhi[i * 4]) = *reinterpret_cast<uint2*>(h);
    *reinterpret_cast<uint2*>(&g_xlo[i * 4]) = *reinterpret_cast<uint2*>(l);
}

// conv_w + fused histogram over dst (runs after conv_x's zero, same stream)
__global__ void conv_w_kernel(const float* __restrict__ Wq,
                              const float* __restrict__ Wk,
                              const float* __restrict__ Wv,
                              const int* __restrict__ dst) {
    int id = blockIdx.x * blockDim.x + threadIdx.x;  // 3*65536 = 196608 threads
    int nthreads = gridDim.x * blockDim.x;
    for (int e = id; e < N_EDGES; e += nthreads)
        atomicAdd(&g_deg[dst[e]], 1);
    if (id >= NTOT * D_MODEL) return;
    int p = id >> 16;          // proj
    int r = id & 65535;
    int k = r & 255;
    int n = r >> 8;
    const float* W = (p == 0) ? Wq : (p == 1) ? Wk : Wv;
    float v = W[k * QKV + n];
    __nv_bfloat16 h = __float2bfloat16_rn(v);
    __nv_bfloat16 l = __float2bfloat16_rn(v - __bfloat162float(h));
    g_wthi[id] = h;
    g_wtlo[id] = l;
}

// =============== mma.sync bf16 GEMM: C[50000,768] = X[50000,256] @ W[256,768] ===============
// 3 split terms folded into K loop (K_eff = 768): term0 hi*hi, term1 lo*hi, term2 hi*lo.
// CTA tile 128x128, warp tile 64x32, BK=64, 2-stage cp.async pipeline (measured
// best: 161.7us; 3-stage regressed to 174.5 — kernel is jointly L1/tensor-bound,
// not CP_WAIT-latency-bound). __launch_bounds__(256,2): 2 CTAs/SM (127 regs).
#define GEMM_STAGE_BYTES 32768          // A 16KB + B 16KB
#define GEMM_SMEM (2 * GEMM_STAGE_BYTES)

__device__ __forceinline__ void gemm_load_stage(uint32_t sbase, int s, int it,
                                                int tileM, int nbase, int tid) {
    const int term = it >> 2;
    const int k0   = (it & 3) * 64;
    const __nv_bfloat16* __restrict__ As = (term == 1) ? g_xlo : g_xhi;
    const __nv_bfloat16* __restrict__ Bs = (term == 2) ? g_wtlo : g_wthi;
    uint32_t aBase = sbase + s * GEMM_STAGE_BYTES;
    uint32_t bBase = aBase + 16384;
    #pragma unroll
    for (int i = 0; i < 4; i++) {
        int idx = tid + i * 256;          // 0..1023
        int row = idx >> 3;
        int c   = idx & 7;
        uint32_t soff = (uint32_t)row * 128u + (uint32_t)((c ^ (row & 7)) << 4);
        int grow = tileM + row;
        if (grow >= N_NODES) grow = 0;    // garbage only pollutes invalid output rows
        cp_async16(aBase + soff, As + (size_t)grow * D_MODEL + k0 + c * 8);
        int nrow = nbase + row;
        cp_async16(bBase + soff, Bs + (size_t)nrow * D_MODEL + k0 + c * 8);
    }
}

__global__ __launch_bounds__(256, 2) void gemm_mma(void) {
    extern __shared__ char smem[];
    const uint32_t sbase = smem_u32(smem);
    const int tid  = threadIdx.x;
    const int lane = tid & 31;
    const int wid  = tid >> 5;
    const int tileM = blockIdx.x * 128;
    const int nbase = blockIdx.y * 128;
    const int wm = wid & 1;      // m sub-tile (64)
    const int wn = wid >> 1;     // n sub-tile (32)

    // hoisted ldmatrix address components
    uint32_t aRowOff[4], bRowOff[4];
    int aR7, bR7;
    {
        int arow = wm * 64 + (lane & 15);
        aR7 = arow & 7;
        #pragma unroll
        for (int mi = 0; mi < 4; mi++)
            aRowOff[mi] = (uint32_t)(arow + mi * 16) * 128u;
        int l16 = lane & 15;
        int brow = wn * 32 + (l16 & 7);
        bR7 = brow & 7;
        #pragma unroll
        for (int ni = 0; ni < 4; ni++)
            bRowOff[ni] = (uint32_t)(brow + ni * 8) * 128u;
    }
    const int aCsel = (lane >> 4);        // 0/1
    const int bCsel = ((lane & 15) >> 3); // 0/1

    float acc[4][4][4];
    #pragma unroll
    for (int mi = 0; mi < 4; mi++)
        #pragma unroll
        for (int ni = 0; ni < 4; ni++)
            #pragma unroll
            for (int r = 0; r < 4; r++) acc[mi][ni][r] = 0.f;

    gemm_load_stage(sbase, 0, 0, tileM, nbase, tid);
    CP_COMMIT();

    int s = 0;
    for (int it = 0; it < 12; ++it) {
        if (it + 1 < 12) {
            gemm_load_stage(sbase, s ^ 1, it + 1, tileM, nbase, tid);
            CP_COMMIT();
            CP_WAIT(1);
        } else {
            CP_COMMIT();
            CP_WAIT(0);
        }
        __syncthreads();

        uint32_t aBase = sbase + (uint32_t)s * GEMM_STAGE_BYTES;
        uint32_t bBase = aBase + 16384;
        #pragma unroll
        for (int k16 = 0; k16 < 4; k16++) {
            uint32_t a[4][4];
            #pragma unroll
            for (int mi = 0; mi < 4; mi++) {
                int cc = k16 * 2 + aCsel;
                uint32_t addr = aBase + aRowOff[mi] + (uint32_t)((cc ^ aR7) << 4);
                ldmatrix_x4(a[mi][0], a[mi][1], a[mi][2], a[mi][3], addr);
            }
            uint32_t b[4][2];
            #pragma unroll
            for (int ni = 0; ni < 4; ni++) {
                int cc = k16 * 2 + bCsel;
                uint32_t addr = bBase + bRowOff[ni] + (uint32_t)((cc ^ bR7) << 4);
                ldmatrix_x2(b[ni][0], b[ni][1], addr);
            }
            #pragma unroll
            for (int mi = 0; mi < 4; mi++)
                #pragma unroll
                for (int ni = 0; ni < 4; ni++)
                    mma_bf16(acc[mi][ni], a[mi], b[ni]);
        }
        s ^= 1;
        __syncthreads();
    }

    // epilogue: q -> g_q[m][col]; k -> g_kv[m][col]; v -> g_kv[m][256+col]
    #pragma unroll
    for (int mi = 0; mi < 4; mi++) {
        #pragma unroll
        for (int ni = 0; ni < 4; ni++) {
            int m0 = tileM + wm * 64 + mi * 16 + (lane >> 2);
            int ng = nbase + wn * 32 + ni * 8 + (lane & 3) * 2;
            int proj = ng >> 8;
            int col  = ng & 255;
            if (m0 < N_NODES) {
                float* dstp = (proj == 0)
                    ? g_q  + (size_t)m0 * QKV + col
                    : g_kv + (size_t)m0 * 512 + (proj == 2 ? 256 : 0) + col;
                *reinterpret_cast<float2*>(dstp) = make_float2(acc[mi][ni][0], acc[mi][ni][1]);
            }
            if (m0 + 8 < N_NODES) {
                float* dstp = (proj == 0)
                    ? g_q  + (size_t)(m0 + 8) * QKV + col
                    : g_kv + (size_t)(m0 + 8) * 512 + (proj == 2 ? 256 : 0) + col;
                *reinterpret_cast<float2*>(dstp) = make_float2(acc[mi][ni][2], acc[mi][ni][3]);
            }
        }
    }
}

// =============== edge binning ===============
__global__ __launch_bounds__(256) void scan_partial() {
    __shared__ int sh[256];
    int tid = threadIdx.x;
    int i = blockIdx.x * 256 + tid;
    int v = (i < N_NODES) ? g_deg[i] : 0;
    sh[tid] = v;
    __syncthreads();
    #pragma unroll
    for (int o = 1; o < 256; o <<= 1) {
        int t = (tid >= o) ? sh[tid - o] : 0;
        __syncthreads();
        sh[tid] += t;
        __syncthreads();
    }
    if (i < N_NODES) g_off[i] = sh[tid] - v;     // exclusive within block
    if (tid == 255) g_bsum[blockIdx.x] = sh[255];
}
__global__ __launch_bounds__(256) void scan_bsums() {
    __shared__ int sh[256];
    int tid = threadIdx.x;
    int v = (tid < N_SBLK) ? g_bsum[tid] : 0;
    sh[tid] = v;
    __syncthreads();
    #pragma unroll
    for (int o = 1; o < 256; o <<= 1) {
        int t = (tid >= o) ? sh[tid - o] : 0;
        __syncthreads();
        sh[tid] += t;
        __syncthreads();
    }
    if (tid < N_SBLK) g_bsum[tid] = sh[tid] - v;  // exclusive block offsets
    if (tid == 0) g_off[N_NODES] = N_EDGES;
}
__global__ void scan_add() {
    int i = blockIdx.x * 256 + threadIdx.x;
    if (i < N_NODES) {
        int t = g_off[i] + g_bsum[blockIdx.x];
        g_off[i] = t;
        g_cur[i] = t;
    }
}
__global__ void scatter_kernel(const int* __restrict__ src, const int* __restrict__ dst) {
    int i = blockIdx.x * blockDim.x + threadIdx.x;
    if (i < N_EDGES) {
        int p = atomicAdd(&g_cur[dst[i]], 1);
        g_srcs[p] = src[i];
    }
}

// =============== per-node attention (warp per node, contiguous-lane layout) ===============
__global__ __launch_bounds__(256) void node_attn_kernel(float* __restrict__ out) {
    const int warp = (blockIdx.x * blockDim.x + threadIdx.x) >> 5;
    const int lane = threadIdx.x & 31;
    if (warp >= N_NODES) return;
    const int n = warp;
    const int beg = g_off[n];
    const int end = g_off[n + 1];

    const float* qp = g_q + (size_t)n * QKV + lane * 8;
    const float4 q0 = *reinterpret_cast<const float4*>(qp);
    const float4 q1 = *reinterpret_cast<const float4*>(qp + 4);

    float a0 = 0.f, a1 = 0.f, a2 = 0.f, a3 = 0.f;
    float a4 = 0.f, a5 = 0.f, a6 = 0.f, a7 = 0.f;
    float z = 0.f;

    const float isd = 0.17677669529663687f;  // 1/sqrt(32)
    const unsigned FULL = 0xffffffffu;

    if (beg < end) {
        const float* kp = g_kv + (size_t)g_srcs[beg] * 512 + lane * 8;
        float4 k0 = *reinterpret_cast<const float4*>(kp);
        float4 k1 = *reinterpret_cast<const float4*>(kp + 4);
        float4 v0 = *reinterpret_cast<const float4*>(kp + 256);
        float4 v1 = *reinterpret_cast<const float4*>(kp + 260);

        for (int i = beg; i < end; i++) {
            int nidx = i + 1 < end ? i + 1 : i;       // clamped prefetch index
            const float* np = g_kv + (size_t)g_srcs[nidx] * 512 + lane * 8;
            float4 nk0 = *reinterpret_cast<const float4*>(np);
            float4 nk1 = *reinterpret_cast<const float4*>(np + 4);
            float4 nv0 = *reinterpret_cast<const float4*>(np + 256);
            float4 nv1 = *reinterpret_cast<const float4*>(np + 260);

            float p = k0.x * q0.x;
            p = fmaf(k0.y, q0.y, p);
            p = fmaf(k0.z, q0.z, p);
            p = fmaf(k0.w, q0.w, p);
            p = fmaf(k1.x, q1.x, p);
            p = fmaf(k1.y, q1.y, p);
            p = fmaf(k1.z, q1.z, p);
            p = fmaf(k1.w, q1.w, p);
            p += __shfl_xor_sync(FULL, p, 1);
            p += __shfl_xor_sync(FULL, p, 2);
            // p = full head dot, replicated on the head's 4 lanes

            float e = __expf(fminf(fmaxf(p * isd, -5.f), 5.f));
            z += e;
            a0 = fmaf(v0.x, e, a0);
            a1 = fmaf(v0.y, e, a1);
            a2 = fmaf(v0.z, e, a2);
            a3 = fmaf(v0.w, e, a3);
            a4 = fmaf(v1.x, e, a4);
            a5 = fmaf(v1.y, e, a5);
            a6 = fmaf(v1.z, e, a6);
            a7 = fmaf(v1.w, e, a7);

            k0 = nk0; k1 = nk1; v0 = nv0; v1 = nv1;
        }
    }

    const float rz = 1.f / (z + 1e-9f);
    float* op = out + (size_t)n * QKV + lane * 8;
    *reinterpret_cast<float4*>(op)     = make_float4(a0 * rz, a1 * rz, a2 * rz, a3 * rz);
    *reinterpret_cast<float4*>(op + 4) = make_float4(a4 * rz, a5 * rz, a6 * rz, a7 * rz);
}

// =============== launch ===============
// Single stream; kernel launches + one cudaFuncSetAttribute only.
// gemm_mma at launch index 3 (the slot ncu samples); scan_partial (needs only
// g_deg, complete after launch 1) fills slot 2.
extern "C" void kernel_launch(void* const* d_in, const int* in_sizes, int n_in,
                              void* d_out, int out_size) {
    const float* x   = (const float*)d_in[0];
    const float* Wq  = (const float*)d_in[1];
    const float* Wk  = (const float*)d_in[2];
    const float* Wv  = (const float*)d_in[3];
    const int*   src = (const int*)d_in[4];
    const int*   dst = (const int*)d_in[5];
    float* out = (float*)d_out;

    cudaFuncSetAttribute(gemm_mma, cudaFuncAttributeMaxDynamicSharedMemorySize, GEMM_SMEM);

    // 0: bf16 split of x (+ zero g_deg)
    conv_x_kernel<<<(N_NODES * D_MODEL / 4 + 255) / 256, 256>>>(x);
    // 1: bf16 split of W (+ histogram of dst)
    conv_w_kernel<<<(NTOT * D_MODEL + 255) / 256, 256>>>(Wq, Wk, Wv, dst);
    // 2: per-block exclusive scan of degrees
    scan_partial<<<N_SBLK, 256>>>();
    // 3: fused QKV GEMM on tensor cores  <-- profiled launch
    dim3 ggrid((N_NODES + 127) / 128, NTOT / 128);
    gemm_mma<<<ggrid, 256, GEMM_SMEM>>>();
    // 4-6: finish binning
    scan_bsums<<<1, 256>>>();
    scan_add<<<N_SBLK, 256>>>();
    scatter_kernel<<<(N_EDGES + 255) / 256, 256>>>(src, dst);
    // 7: per-node attention + normalization
    node_attn_kernel<<<(N_NODES * 32 + 255) / 256, 256>>>(out);
}

// round 15
// speedup vs baseline: 1.1831x; 1.1758x over previous
#include <cuda_runtime.h>
#include <cuda_bf16.h>
#include <cuda_fp16.h>
#include <stdint.h>
#include <math.h>

#define N_NODES 50000
#define N_EDGES 800000
#define D_MODEL 256
#define HEADS   8
#define D_K     32
#define QKV     256
#define NTOT    768   // q|k|v concatenated

// ---------------- scratch ----------------
__device__ float g_q[N_NODES * QKV];
// k/v stored fp16 for the gather phase: per node 1024B = 512 halves
// ([0,256)=k, [256,512)=v). uint4-typed for guaranteed 16B alignment.
__device__ uint4 g_kv4[N_NODES * 64];
__device__ __nv_bfloat16 g_xhi[N_NODES * D_MODEL];
__device__ __nv_bfloat16 g_xlo[N_NODES * D_MODEL];
__device__ __nv_bfloat16 g_wthi[NTOT * D_MODEL];   // W^T rows: n in [0,768), k in [0,256)
__device__ __nv_bfloat16 g_wtlo[NTOT * D_MODEL];
__device__ int g_deg[N_NODES];
__device__ int g_off[N_NODES + 1];
__device__ int g_cur[N_NODES];
__device__ int g_srcs[N_EDGES];
#define N_SBLK ((N_NODES + 255) / 256)
__device__ int g_bsum[N_SBLK];

// ---------------- PTX helpers (plain sm_100-legal) ----------------
__device__ __forceinline__ uint32_t smem_u32(const void* p) {
    uint32_t a;
    asm("{ .reg .u64 t; cvta.to.shared.u64 t, %1; cvt.u32.u64 %0, t; }" : "=r"(a) : "l"(p));
    return a;
}
__device__ __forceinline__ void cp_async16(uint32_t daddr, const void* gptr) {
    asm volatile("cp.async.cg.shared.global [%0], [%1], 16;" :: "r"(daddr), "l"(gptr) : "memory");
}
#define CP_COMMIT() asm volatile("cp.async.commit_group;" ::: "memory")
#define CP_WAIT(n)  asm volatile("cp.async.wait_group %0;" :: "n"(n) : "memory")

__device__ __forceinline__ void ldmatrix_x4(uint32_t& a0, uint32_t& a1, uint32_t& a2, uint32_t& a3, uint32_t addr) {
    asm volatile("ldmatrix.sync.aligned.m8n8.x4.shared.b16 {%0,%1,%2,%3}, [%4];"
                 : "=r"(a0), "=r"(a1), "=r"(a2), "=r"(a3) : "r"(addr));
}
__device__ __forceinline__ void ldmatrix_x2(uint32_t& b0, uint32_t& b1, uint32_t addr) {
    asm volatile("ldmatrix.sync.aligned.m8n8.x2.shared.b16 {%0,%1}, [%2];"
                 : "=r"(b0), "=r"(b1) : "r"(addr));
}
__device__ __forceinline__ void mma_bf16(float* d, const uint32_t* a, const uint32_t* b) {
    asm volatile(
        "mma.sync.aligned.m16n8k16.row.col.f32.bf16.bf16.f32 "
        "{%0,%1,%2,%3}, {%4,%5,%6,%7}, {%8,%9}, {%0,%1,%2,%3};"
        : "+f"(d[0]), "+f"(d[1]), "+f"(d[2]), "+f"(d[3])
        : "r"(a[0]), "r"(a[1]), "r"(a[2]), "r"(a[3]), "r"(b[0]), "r"(b[1]));
}

// unpack 8 fp16 (one uint4) into 8 floats
__device__ __forceinline__ void h8_to_f(const uint4& r, float* f) {
    const __half2* h = reinterpret_cast<const __half2*>(&r);
    float2 t;
    t = __half22float2(h[0]); f[0] = t.x; f[1] = t.y;
    t = __half22float2(h[1]); f[2] = t.x; f[3] = t.y;
    t = __half22float2(h[2]); f[4] = t.x; f[5] = t.y;
    t = __half22float2(h[3]); f[6] = t.x; f[7] = t.y;
}

// =============== bf16 split conversion (+ fused binning pre-work) ===============
__global__ void conv_x_kernel(const float* __restrict__ x) {
    int i = blockIdx.x * blockDim.x + threadIdx.x;   // float4 index
    if (i < N_NODES) g_deg[i] = 0;                    // fused zero of degree array
    if (i >= N_NODES * D_MODEL / 4) return;
    float4 f = *reinterpret_cast<const float4*>(x + i * 4);
    __nv_bfloat16 h[4], l[4];
    float vv[4] = {f.x, f.y, f.z, f.w};
    #pragma unroll
    for (int j = 0; j < 4; j++) {
        h[j] = __float2bfloat16_rn(vv[j]);
        l[j] = __float2bfloat16_rn(vv[j] - __bfloat162float(h[j]));
    }
    *reinterpret_cast<uint2*>(&g_xhi[i * 4]) = *reinterpret_cast<uint2*>(h);
    *reinterpret_cast<uint2*>(&g_xlo[i * 4]) = *reinterpret_cast<uint2*>(l);
}

// conv_w + fused histogram over dst
__global__ void conv_w_kernel(const float* __restrict__ Wq,
                              const float* __restrict__ Wk,
                              const float* __restrict__ Wv,
                              const int* __restrict__ dst) {
    int id = blockIdx.x * blockDim.x + threadIdx.x;  // 3*65536 = 196608 threads
    int nthreads = gridDim.x * blockDim.x;
    for (int e = id; e < N_EDGES; e += nthreads)
        atomicAdd(&g_deg[dst[e]], 1);
    if (id >= NTOT * D_MODEL) return;
    int p = id >> 16;          // proj
    int r = id & 65535;
    int k = r & 255;
    int n = r >> 8;
    const float* W = (p == 0) ? Wq : (p == 1) ? Wk : Wv;
    float v = W[k * QKV + n];
    __nv_bfloat16 h = __float2bfloat16_rn(v);
    __nv_bfloat16 l = __float2bfloat16_rn(v - __bfloat162float(h));
    g_wthi[id] = h;
    g_wtlo[id] = l;
}

// =============== mma.sync bf16 GEMM: C[50000,768] = X[50000,256] @ W[256,768] ===============
// 3 split terms folded into K loop (K_eff = 768). CTA 128x128, warp 64x32,
// BK=64, 2-stage cp.async (measured best; 3-stage regressed).
// __launch_bounds__(256,2): 2 CTAs/SM (127 regs measured).
#define GEMM_STAGE_BYTES 32768          // A 16KB + B 16KB
#define GEMM_SMEM (2 * GEMM_STAGE_BYTES)

__device__ __forceinline__ void gemm_load_stage(uint32_t sbase, int s, int it,
                                                int tileM, int nbase, int tid) {
    const int term = it >> 2;
    const int k0   = (it & 3) * 64;
    const __nv_bfloat16* __restrict__ As = (term == 1) ? g_xlo : g_xhi;
    const __nv_bfloat16* __restrict__ Bs = (term == 2) ? g_wtlo : g_wthi;
    uint32_t aBase = sbase + s * GEMM_STAGE_BYTES;
    uint32_t bBase = aBase + 16384;
    #pragma unroll
    for (int i = 0; i < 4; i++) {
        int idx = tid + i * 256;          // 0..1023
        int row = idx >> 3;
        int c   = idx & 7;
        uint32_t soff = (uint32_t)row * 128u + (uint32_t)((c ^ (row & 7)) << 4);
        int grow = tileM + row;
        if (grow >= N_NODES) grow = 0;    // garbage only pollutes invalid output rows
        cp_async16(aBase + soff, As + (size_t)grow * D_MODEL + k0 + c * 8);
        int nrow = nbase + row;
        cp_async16(bBase + soff, Bs + (size_t)nrow * D_MODEL + k0 + c * 8);
    }
}

__global__ __launch_bounds__(256, 2) void gemm_mma(void) {
    extern __shared__ char smem[];
    const uint32_t sbase = smem_u32(smem);
    const int tid  = threadIdx.x;
    const int lane = tid & 31;
    const int wid  = tid >> 5;
    const int tileM = blockIdx.x * 128;
    const int nbase = blockIdx.y * 128;
    const int wm = wid & 1;      // m sub-tile (64)
    const int wn = wid >> 1;     // n sub-tile (32)

    // hoisted ldmatrix address components
    uint32_t aRowOff[4], bRowOff[4];
    int aR7, bR7;
    {
        int arow = wm * 64 + (lane & 15);
        aR7 = arow & 7;
        #pragma unroll
        for (int mi = 0; mi < 4; mi++)
            aRowOff[mi] = (uint32_t)(arow + mi * 16) * 128u;
        int l16 = lane & 15;
        int brow = wn * 32 + (l16 & 7);
        bR7 = brow & 7;
        #pragma unroll
        for (int ni = 0; ni < 4; ni++)
            bRowOff[ni] = (uint32_t)(brow + ni * 8) * 128u;
    }
    const int aCsel = (lane >> 4);        // 0/1
    const int bCsel = ((lane & 15) >> 3); // 0/1

    float acc[4][4][4];
    #pragma unroll
    for (int mi = 0; mi < 4; mi++)
        #pragma unroll
        for (int ni = 0; ni < 4; ni++)
            #pragma unroll
            for (int r = 0; r < 4; r++) acc[mi][ni][r] = 0.f;

    gemm_load_stage(sbase, 0, 0, tileM, nbase, tid);
    CP_COMMIT();

    int s = 0;
    for (int it = 0; it < 12; ++it) {
        if (it + 1 < 12) {
            gemm_load_stage(sbase, s ^ 1, it + 1, tileM, nbase, tid);
            CP_COMMIT();
            CP_WAIT(1);
        } else {
            CP_COMMIT();
            CP_WAIT(0);
        }
        __syncthreads();

        uint32_t aBase = sbase + (uint32_t)s * GEMM_STAGE_BYTES;
        uint32_t bBase = aBase + 16384;
        #pragma unroll
        for (int k16 = 0; k16 < 4; k16++) {
            uint32_t a[4][4];
            #pragma unroll
            for (int mi = 0; mi < 4; mi++) {
                int cc = k16 * 2 + aCsel;
                uint32_t addr = aBase + aRowOff[mi] + (uint32_t)((cc ^ aR7) << 4);
                ldmatrix_x4(a[mi][0], a[mi][1], a[mi][2], a[mi][3], addr);
            }
            uint32_t b[4][2];
            #pragma unroll
            for (int ni = 0; ni < 4; ni++) {
                int cc = k16 * 2 + bCsel;
                uint32_t addr = bBase + bRowOff[ni] + (uint32_t)((cc ^ bR7) << 4);
                ldmatrix_x2(b[ni][0], b[ni][1], addr);
            }
            #pragma unroll
            for (int mi = 0; mi < 4; mi++)
                #pragma unroll
                for (int ni = 0; ni < 4; ni++)
                    mma_bf16(acc[mi][ni], a[mi], b[ni]);
        }
        s ^= 1;
        __syncthreads();
    }

    // epilogue: q (fp32) -> g_q; k/v (fp16 half2) -> g_kv4 region
    #pragma unroll
    for (int mi = 0; mi < 4; mi++) {
        #pragma unroll
        for (int ni = 0; ni < 4; ni++) {
            int m0 = tileM + wm * 64 + mi * 16 + (lane >> 2);
            int ng = nbase + wn * 32 + ni * 8 + (lane & 3) * 2;
            int proj = ng >> 8;
            int col  = ng & 255;
            int kvoff = (proj == 2 ? 128 : 0) + (col >> 1);   // half2 index within node
            if (m0 < N_NODES) {
                if (proj == 0) {
                    *reinterpret_cast<float2*>(g_q + (size_t)m0 * QKV + col) =
                        make_float2(acc[mi][ni][0], acc[mi][ni][1]);
                } else {
                    __half2* dstp = reinterpret_cast<__half2*>(g_kv4 + (size_t)m0 * 64) + kvoff;
                    *dstp = __floats2half2_rn(acc[mi][ni][0], acc[mi][ni][1]);
                }
            }
            if (m0 + 8 < N_NODES) {
                if (proj == 0) {
                    *reinterpret_cast<float2*>(g_q + (size_t)(m0 + 8) * QKV + col) =
                        make_float2(acc[mi][ni][2], acc[mi][ni][3]);
                } else {
                    __half2* dstp = reinterpret_cast<__half2*>(g_kv4 + (size_t)(m0 + 8) * 64) + kvoff;
                    *dstp = __floats2half2_rn(acc[mi][ni][2], acc[mi][ni][3]);
                }
            }
        }
    }
}

// =============== edge binning ===============
__global__ __launch_bounds__(256) void scan_partial() {
    __shared__ int sh[256];
    int tid = threadIdx.x;
    int i = blockIdx.x * 256 + tid;
    int v = (i < N_NODES) ? g_deg[i] : 0;
    sh[tid] = v;
    __syncthreads();
    #pragma unroll
    for (int o = 1; o < 256; o <<= 1) {
        int t = (tid >= o) ? sh[tid - o] : 0;
        __syncthreads();
        sh[tid] += t;
        __syncthreads();
    }
    if (i < N_NODES) g_off[i] = sh[tid] - v;     // exclusive within block
    if (tid == 255) g_bsum[blockIdx.x] = sh[255];
}
__global__ __launch_bounds__(256) void scan_bsums() {
    __shared__ int sh[256];
    int tid = threadIdx.x;
    int v = (tid < N_SBLK) ? g_bsum[tid] : 0;
    sh[tid] = v;
    __syncthreads();
    #pragma unroll
    for (int o = 1; o < 256; o <<= 1) {
        int t = (tid >= o) ? sh[tid - o] : 0;
        __syncthreads();
        sh[tid] += t;
        __syncthreads();
    }
    if (tid < N_SBLK) g_bsum[tid] = sh[tid] - v;  // exclusive block offsets
    if (tid == 0) g_off[N_NODES] = N_EDGES;
}
__global__ void scan_add() {
    int i = blockIdx.x * 256 + threadIdx.x;
    if (i < N_NODES) {
        int t = g_off[i] + g_bsum[blockIdx.x];
        g_off[i] = t;
        g_cur[i] = t;
    }
}
__global__ void scatter_kernel(const int* __restrict__ src, const int* __restrict__ dst) {
    int i = blockIdx.x * blockDim.x + threadIdx.x;
    if (i < N_EDGES) {
        int p = atomicAdd(&g_cur[dst[i]], 1);
        g_srcs[p] = src[i];
    }
}

// =============== per-node attention (warp per node, fp16 k/v gather) ===============
// Lane l owns columns [8l, 8l+8); head h = l>>2 spans 4 lanes. Per edge the
// warp gathers one 1KB fp16 region: 2 x LDG.128 per lane (k, v), converts to
// fp32, does all math in fp32. Clamped-index prefetch hides L2 latency.
__global__ __launch_bounds__(256) void node_attn_kernel(float* __restrict__ out) {
    const int warp = (blockIdx.x * blockDim.x + threadIdx.x) >> 5;
    const int lane = threadIdx.x & 31;
    if (warp >= N_NODES) return;
    const int n = warp;
    const int beg = g_off[n];
    const int end = g_off[n + 1];

    const float* qp = g_q + (size_t)n * QKV + lane * 8;
    const float4 q0 = *reinterpret_cast<const float4*>(qp);
    const float4 q1 = *reinterpret_cast<const float4*>(qp + 4);
    float qf[8] = {q0.x, q0.y, q0.z, q0.w, q1.x, q1.y, q1.z, q1.w};

    float af[8];
    #pragma unroll
    for (int j = 0; j < 8; j++) af[j] = 0.f;
    float z = 0.f;

    const float isd = 0.17677669529663687f;  // 1/sqrt(32)
    const unsigned FULL = 0xffffffffu;

    if (beg < end) {
        const uint4* kp0 = reinterpret_cast<const uint4*>(
            reinterpret_cast<const __half*>(g_kv4 + (size_t)g_srcs[beg] * 64) + lane * 8);
        uint4 kr = kp0[0];
        uint4 vr = kp0[32];   // +256 halves = +32 uint4

        for (int i = beg; i < end; i++) {
            int nidx = i + 1 < end ? i + 1 : i;       // clamped prefetch index
            const uint4* np = reinterpret_cast<const uint4*>(
                reinterpret_cast<const __half*>(g_kv4 + (size_t)g_srcs[nidx] * 64) + lane * 8);
            uint4 nkr = np[0];
            uint4 nvr = np[32];

            float kf[8], vf[8];
            h8_to_f(kr, kf);
            h8_to_f(vr, vf);

            float p = kf[0] * qf[0];
            #pragma unroll
            for (int j = 1; j < 8; j++) p = fmaf(kf[j], qf[j], p);
            p += __shfl_xor_sync(FULL, p, 1);
            p += __shfl_xor_sync(FULL, p, 2);
            // p = full head dot, replicated on the head's 4 lanes

            float e = __expf(fminf(fmaxf(p * isd, -5.f), 5.f));
            z += e;
            #pragma unroll
            for (int j = 0; j < 8; j++) af[j] = fmaf(vf[j], e, af[j]);

            kr = nkr; vr = nvr;
        }
    }

    const float rz = 1.f / (z + 1e-9f);
    float* op = out + (size_t)n * QKV + lane * 8;
    *reinterpret_cast<float4*>(op) =
        make_float4(af[0] * rz, af[1] * rz, af[2] * rz, af[3] * rz);
    *reinterpret_cast<float4*>(op + 4) =
        make_float4(af[4] * rz, af[5] * rz, af[6] * rz, af[7] * rz);
}

// =============== launch ===============
// Single stream; kernel launches + one cudaFuncSetAttribute only.
// gemm_mma at launch index 3 (the slot ncu samples).
extern "C" void kernel_launch(void* const* d_in, const int* in_sizes, int n_in,
                              void* d_out, int out_size) {
    const float* x   = (const float*)d_in[0];
    const float* Wq  = (const float*)d_in[1];
    const float* Wk  = (const float*)d_in[2];
    const float* Wv  = (const float*)d_in[3];
    const int*   src = (const int*)d_in[4];
    const int*   dst = (const int*)d_in[5];
    float* out = (float*)d_out;

    cudaFuncSetAttribute(gemm_mma, cudaFuncAttributeMaxDynamicSharedMemorySize, GEMM_SMEM);

    // 0: bf16 split of x (+ zero g_deg)
    conv_x_kernel<<<(N_NODES * D_MODEL / 4 + 255) / 256, 256>>>(x);
    // 1: bf16 split of W (+ histogram of dst)
    conv_w_kernel<<<(NTOT * D_MODEL + 255) / 256, 256>>>(Wq, Wk, Wv, dst);
    // 2: per-block exclusive scan of degrees
    scan_partial<<<N_SBLK, 256>>>();
    // 3: fused QKV GEMM on tensor cores  <-- profiled launch
    dim3 ggrid((N_NODES + 127) / 128, NTOT / 128);
    gemm_mma<<<ggrid, 256, GEMM_SMEM>>>();
    // 4-6: finish binning
    scan_bsums<<<1, 256>>>();
    scan_add<<<N_SBLK, 256>>>();
    scatter_kernel<<<(N_EDGES + 255) / 256, 256>>>(src, dst);
    // 7: per-node attention + normalization
    node_attn_kernel<<<(N_NODES * 32 + 255) / 256, 256>>>(out);
}

// round 16
// speedup vs baseline: 1.1985x; 1.0130x over previous
#include <cuda_runtime.h>
#include <cuda_bf16.h>
#include <cuda_fp16.h>
#include <stdint.h>
#include <math.h>

#define N_NODES 50000
#define N_EDGES 800000
#define D_MODEL 256
#define HEADS   8
#define D_K     32
#define QKV     256
#define NTOT    768   // q|k|v concatenated

// ---------------- scratch ----------------
__device__ float g_q[N_NODES * QKV];
// k/v stored fp16 for the gather phase: per node 1024B = 512 halves
// ([0,256)=k, [256,512)=v). uint4-typed for guaranteed 16B alignment.
__device__ uint4 g_kv4[N_NODES * 64];
__device__ __nv_bfloat16 g_xhi[N_NODES * D_MODEL];
__device__ __nv_bfloat16 g_xlo[N_NODES * D_MODEL];
__device__ __nv_bfloat16 g_wthi[NTOT * D_MODEL];   // W^T rows: n in [0,768), k in [0,256)
__device__ __nv_bfloat16 g_wtlo[NTOT * D_MODEL];
__device__ int g_deg[N_NODES];
__device__ int g_off[N_NODES + 1];
__device__ int g_cur[N_NODES];
__device__ int g_srcs[N_EDGES];
#define N_SBLK ((N_NODES + 255) / 256)
__device__ int g_bsum[N_SBLK];

// ---------------- PTX helpers (plain sm_100-legal) ----------------
__device__ __forceinline__ uint32_t smem_u32(const void* p) {
    uint32_t a;
    asm("{ .reg .u64 t; cvta.to.shared.u64 t, %1; cvt.u32.u64 %0, t; }" : "=r"(a) : "l"(p));
    return a;
}
__device__ __forceinline__ void cp_async16(uint32_t daddr, const void* gptr) {
    asm volatile("cp.async.cg.shared.global [%0], [%1], 16;" :: "r"(daddr), "l"(gptr) : "memory");
}
#define CP_COMMIT() asm volatile("cp.async.commit_group;" ::: "memory")
#define CP_WAIT(n)  asm volatile("cp.async.wait_group %0;" :: "n"(n) : "memory")

__device__ __forceinline__ void ldmatrix_x4(uint32_t& a0, uint32_t& a1, uint32_t& a2, uint32_t& a3, uint32_t addr) {
    asm volatile("ldmatrix.sync.aligned.m8n8.x4.shared.b16 {%0,%1,%2,%3}, [%4];"
                 : "=r"(a0), "=r"(a1), "=r"(a2), "=r"(a3) : "r"(addr));
}
__device__ __forceinline__ void ldmatrix_x2(uint32_t& b0, uint32_t& b1, uint32_t addr) {
    asm volatile("ldmatrix.sync.aligned.m8n8.x2.shared.b16 {%0,%1}, [%2];"
                 : "=r"(b0), "=r"(b1) : "r"(addr));
}
__device__ __forceinline__ void mma_bf16(float* d, const uint32_t* a, const uint32_t* b) {
    asm volatile(
        "mma.sync.aligned.m16n8k16.row.col.f32.bf16.bf16.f32 "
        "{%0,%1,%2,%3}, {%4,%5,%6,%7}, {%8,%9}, {%0,%1,%2,%3};"
        : "+f"(d[0]), "+f"(d[1]), "+f"(d[2]), "+f"(d[3])
        : "r"(a[0]), "r"(a[1]), "r"(a[2]), "r"(a[3]), "r"(b[0]), "r"(b[1]));
}

// unpack 8 fp16 (one uint4) into 8 floats
__device__ __forceinline__ void h8_to_f(const uint4& r, float* f) {
    const __half2* h = reinterpret_cast<const __half2*>(&r);
    float2 t;
    t = __half22float2(h[0]); f[0] = t.x; f[1] = t.y;
    t = __half22float2(h[1]); f[2] = t.x; f[3] = t.y;
    t = __half22float2(h[2]); f[4] = t.x; f[5] = t.y;
    t = __half22float2(h[3]); f[6] = t.x; f[7] = t.y;
}

// =============== bf16 split conversion (+ fused binning pre-work) ===============
__global__ void conv_x_kernel(const float* __restrict__ x) {
    int i = blockIdx.x * blockDim.x + threadIdx.x;   // float4 index
    if (i < N_NODES) g_deg[i] = 0;                    // fused zero of degree array
    if (i >= N_NODES * D_MODEL / 4) return;
    float4 f = *reinterpret_cast<const float4*>(x + i * 4);
    __nv_bfloat16 h[4], l[4];
    float vv[4] = {f.x, f.y, f.z, f.w};
    #pragma unroll
    for (int j = 0; j < 4; j++) {
        h[j] = __float2bfloat16_rn(vv[j]);
        l[j] = __float2bfloat16_rn(vv[j] - __bfloat162float(h[j]));
    }
    *reinterpret_cast<uint2*>(&g_xhi[i * 4]) = *reinterpret_cast<uint2*>(h);
    *reinterpret_cast<uint2*>(&g_xlo[i * 4]) = *reinterpret_cast<uint2*>(l);
}

// conv_w + fused histogram over dst
__global__ void conv_w_kernel(const float* __restrict__ Wq,
                              const float* __restrict__ Wk,
                              const float* __restrict__ Wv,
                              const int* __restrict__ dst) {
    int id = blockIdx.x * blockDim.x + threadIdx.x;  // 3*65536 = 196608 threads
    int nthreads = gridDim.x * blockDim.x;
    for (int e = id; e < N_EDGES; e += nthreads)
        atomicAdd(&g_deg[dst[e]], 1);
    if (id >= NTOT * D_MODEL) return;
    int p = id >> 16;          // proj
    int r = id & 65535;
    int k = r & 255;
    int n = r >> 8;
    const float* W = (p == 0) ? Wq : (p == 1) ? Wk : Wv;
    float v = W[k * QKV + n];
    __nv_bfloat16 h = __float2bfloat16_rn(v);
    __nv_bfloat16 l = __float2bfloat16_rn(v - __bfloat162float(h));
    g_wthi[id] = h;
    g_wtlo[id] = l;
}

// =============== mma.sync bf16 GEMM: C[50000,768] = X[50000,256] @ W[256,768] ===============
// 3 split terms folded into K loop (K_eff = 768). CTA 128x128, warp 64x32,
// BK=64. 3-stage cp.async pipeline with ONE __syncthreads per iteration:
// wait(stage s) -> barrier -> issue load for it+2 into (s+2)%3 -> compute s.
// The iteration-start barrier proves all warps finished computing (s+2)%3 in
// the previous iteration, so the trailing barrier of the classic scheme is
// deleted (12 barriers instead of 24 — measured ~60us of the 176us gemm was
// neither tensor nor L1 time, attributed to barrier drain).
// __launch_bounds__(256,2): 2 CTAs/SM. SMEM 96KB x2 = 192KB < 228KB.
#define GEMM_STAGE_BYTES 32768          // A 16KB + B 16KB
#define GEMM_STAGES 3
#define GEMM_SMEM (GEMM_STAGES * GEMM_STAGE_BYTES)

__device__ __forceinline__ void gemm_load_stage(uint32_t sbase, int s, int it,
                                                int tileM, int nbase, int tid) {
    const int term = it >> 2;
    const int k0   = (it & 3) * 64;
    const __nv_bfloat16* __restrict__ As = (term == 1) ? g_xlo : g_xhi;
    const __nv_bfloat16* __restrict__ Bs = (term == 2) ? g_wtlo : g_wthi;
    uint32_t aBase = sbase + s * GEMM_STAGE_BYTES;
    uint32_t bBase = aBase + 16384;
    #pragma unroll
    for (int i = 0; i < 4; i++) {
        int idx = tid + i * 256;          // 0..1023
        int row = idx >> 3;
        int c   = idx & 7;
        uint32_t soff = (uint32_t)row * 128u + (uint32_t)((c ^ (row & 7)) << 4);
        int grow = tileM + row;
        if (grow >= N_NODES) grow = 0;    // garbage only pollutes invalid output rows
        cp_async16(aBase + soff, As + (size_t)grow * D_MODEL + k0 + c * 8);
        int nrow = nbase + row;
        cp_async16(bBase + soff, Bs + (size_t)nrow * D_MODEL + k0 + c * 8);
    }
}

__global__ __launch_bounds__(256, 2) void gemm_mma(void) {
    extern __shared__ char smem[];
    const uint32_t sbase = smem_u32(smem);
    const int tid  = threadIdx.x;
    const int lane = tid & 31;
    const int wid  = tid >> 5;
    const int tileM = blockIdx.x * 128;
    const int nbase = blockIdx.y * 128;
    const int wm = wid & 1;      // m sub-tile (64)
    const int wn = wid >> 1;     // n sub-tile (32)

    // hoisted ldmatrix address components
    uint32_t aRowOff[4], bRowOff[4];
    int aR7, bR7;
    {
        int arow = wm * 64 + (lane & 15);
        aR7 = arow & 7;
        #pragma unroll
        for (int mi = 0; mi < 4; mi++)
            aRowOff[mi] = (uint32_t)(arow + mi * 16) * 128u;
        int l16 = lane & 15;
        int brow = wn * 32 + (l16 & 7);
        bR7 = brow & 7;
        #pragma unroll
        for (int ni = 0; ni < 4; ni++)
            bRowOff[ni] = (uint32_t)(brow + ni * 8) * 128u;
    }
    const int aCsel = (lane >> 4);        // 0/1
    const int bCsel = ((lane & 15) >> 3); // 0/1

    float acc[4][4][4];
    #pragma unroll
    for (int mi = 0; mi < 4; mi++)
        #pragma unroll
        for (int ni = 0; ni < 4; ni++)
            #pragma unroll
            for (int r = 0; r < 4; r++) acc[mi][ni][r] = 0.f;

    gemm_load_stage(sbase, 0, 0, tileM, nbase, tid);
    CP_COMMIT();
    gemm_load_stage(sbase, 1, 1, tileM, nbase, tid);
    CP_COMMIT();

    int s = 0;
    for (int it = 0; it < 12; ++it) {
        if (it < 11) { CP_WAIT(1); } else { CP_WAIT(0); }
        __syncthreads();      // stage s visible to all; all warps done with (s+2)%3

        if (it + 2 < 12) {
            int ld = s + 2; if (ld >= GEMM_STAGES) ld -= GEMM_STAGES;
            gemm_load_stage(sbase, ld, it + 2, tileM, nbase, tid);
            CP_COMMIT();
        }

        uint32_t aBase = sbase + (uint32_t)s * GEMM_STAGE_BYTES;
        uint32_t bBase = aBase + 16384;
        #pragma unroll
        for (int k16 = 0; k16 < 4; k16++) {
            uint32_t a[4][4];
            #pragma unroll
            for (int mi = 0; mi < 4; mi++) {
                int cc = k16 * 2 + aCsel;
                uint32_t addr = aBase + aRowOff[mi] + (uint32_t)((cc ^ aR7) << 4);
                ldmatrix_x4(a[mi][0], a[mi][1], a[mi][2], a[mi][3], addr);
            }
            uint32_t b[4][2];
            #pragma unroll
            for (int ni = 0; ni < 4; ni++) {
                int cc = k16 * 2 + bCsel;
                uint32_t addr = bBase + bRowOff[ni] + (uint32_t)((cc ^ bR7) << 4);
                ldmatrix_x2(b[ni][0], b[ni][1], addr);
            }
            #pragma unroll
            for (int mi = 0; mi < 4; mi++)
                #pragma unroll
                for (int ni = 0; ni < 4; ni++)
                    mma_bf16(acc[mi][ni], a[mi], b[ni]);
        }
        if (++s >= GEMM_STAGES) s = 0;
    }

    // epilogue: q (fp32) -> g_q; k/v (fp16 half2) -> g_kv4 region
    #pragma unroll
    for (int mi = 0; mi < 4; mi++) {
        #pragma unroll
        for (int ni = 0; ni < 4; ni++) {
            int m0 = tileM + wm * 64 + mi * 16 + (lane >> 2);
            int ng = nbase + wn * 32 + ni * 8 + (lane & 3) * 2;
            int proj = ng >> 8;
            int col  = ng & 255;
            int kvoff = (proj == 2 ? 128 : 0) + (col >> 1);   // half2 index within node
            if (m0 < N_NODES) {
                if (proj == 0) {
                    *reinterpret_cast<float2*>(g_q + (size_t)m0 * QKV + col) =
                        make_float2(acc[mi][ni][0], acc[mi][ni][1]);
                } else {
                    __half2* dstp = reinterpret_cast<__half2*>(g_kv4 + (size_t)m0 * 64) + kvoff;
                    *dstp = __floats2half2_rn(acc[mi][ni][0], acc[mi][ni][1]);
                }
            }
            if (m0 + 8 < N_NODES) {
                if (proj == 0) {
                    *reinterpret_cast<float2*>(g_q + (size_t)(m0 + 8) * QKV + col) =
                        make_float2(acc[mi][ni][2], acc[mi][ni][3]);
                } else {
                    __half2* dstp = reinterpret_cast<__half2*>(g_kv4 + (size_t)(m0 + 8) * 64) + kvoff;
                    *dstp = __floats2half2_rn(acc[mi][ni][2], acc[mi][ni][3]);
                }
            }
        }
    }
}

// =============== edge binning ===============
__global__ __launch_bounds__(256) void scan_partial() {
    __shared__ int sh[256];
    int tid = threadIdx.x;
    int i = blockIdx.x * 256 + tid;
    int v = (i < N_NODES) ? g_deg[i] : 0;
    sh[tid] = v;
    __syncthreads();
    #pragma unroll
    for (int o = 1; o < 256; o <<= 1) {
        int t = (tid >= o) ? sh[tid - o] : 0;
        __syncthreads();
        sh[tid] += t;
        __syncthreads();
    }
    if (i < N_NODES) g_off[i] = sh[tid] - v;     // exclusive within block
    if (tid == 255) g_bsum[blockIdx.x] = sh[255];
}
__global__ __launch_bounds__(256) void scan_bsums() {
    __shared__ int sh[256];
    int tid = threadIdx.x;
    int v = (tid < N_SBLK) ? g_bsum[tid] : 0;
    sh[tid] = v;
    __syncthreads();
    #pragma unroll
    for (int o = 1; o < 256; o <<= 1) {
        int t = (tid >= o) ? sh[tid - o] : 0;
        __syncthreads();
        sh[tid] += t;
        __syncthreads();
    }
    if (tid < N_SBLK) g_bsum[tid] = sh[tid] - v;  // exclusive block offsets
    if (tid == 0) g_off[N_NODES] = N_EDGES;
}
__global__ void scan_add() {
    int i = blockIdx.x * 256 + threadIdx.x;
    if (i < N_NODES) {
        int t = g_off[i] + g_bsum[blockIdx.x];
        g_off[i] = t;
        g_cur[i] = t;
    }
}
__global__ void scatter_kernel(const int* __restrict__ src, const int* __restrict__ dst) {
    int i = blockIdx.x * blockDim.x + threadIdx.x;
    if (i < N_EDGES) {
        int p = atomicAdd(&g_cur[dst[i]], 1);
        g_srcs[p] = src[i];
    }
}

// =============== per-node attention (warp per node, fp16 k/v gather) ===============
__global__ __launch_bounds__(256) void node_attn_kernel(float* __restrict__ out) {
    const int warp = (blockIdx.x * blockDim.x + threadIdx.x) >> 5;
    const int lane = threadIdx.x & 31;
    if (warp >= N_NODES) return;
    const int n = warp;
    const int beg = g_off[n];
    const int end = g_off[n + 1];

    const float* qp = g_q + (size_t)n * QKV + lane * 8;
    const float4 q0 = *reinterpret_cast<const float4*>(qp);
    const float4 q1 = *reinterpret_cast<const float4*>(qp + 4);
    float qf[8] = {q0.x, q0.y, q0.z, q0.w, q1.x, q1.y, q1.z, q1.w};

    float af[8];
    #pragma unroll
    for (int j = 0; j < 8; j++) af[j] = 0.f;
    float z = 0.f;

    const float isd = 0.17677669529663687f;  // 1/sqrt(32)
    const unsigned FULL = 0xffffffffu;

    if (beg < end) {
        const uint4* kp0 = reinterpret_cast<const uint4*>(
            reinterpret_cast<const __half*>(g_kv4 + (size_t)g_srcs[beg] * 64) + lane * 8);
        uint4 kr = kp0[0];
        uint4 vr = kp0[32];   // +256 halves = +32 uint4

        for (int i = beg; i < end; i++) {
            int nidx = i + 1 < end ? i + 1 : i;       // clamped prefetch index
            const uint4* np = reinterpret_cast<const uint4*>(
                reinterpret_cast<const __half*>(g_kv4 + (size_t)g_srcs[nidx] * 64) + lane * 8);
            uint4 nkr = np[0];
            uint4 nvr = np[32];

            float kf[8], vf[8];
            h8_to_f(kr, kf);
            h8_to_f(vr, vf);

            float p = kf[0] * qf[0];
            #pragma unroll
            for (int j = 1; j < 8; j++) p = fmaf(kf[j], qf[j], p);
            p += __shfl_xor_sync(FULL, p, 1);
            p += __shfl_xor_sync(FULL, p, 2);
            // p = full head dot, replicated on the head's 4 lanes

            float e = __expf(fminf(fmaxf(p * isd, -5.f), 5.f));
            z += e;
            #pragma unroll
            for (int j = 0; j < 8; j++) af[j] = fmaf(vf[j], e, af[j]);

            kr = nkr; vr = nvr;
        }
    }

    const float rz = 1.f / (z + 1e-9f);
    float* op = out + (size_t)n * QKV + lane * 8;
    *reinterpret_cast<float4*>(op) =
        make_float4(af[0] * rz, af[1] * rz, af[2] * rz, af[3] * rz);
    *reinterpret_cast<float4*>(op + 4) =
        make_float4(af[4] * rz, af[5] * rz, af[6] * rz, af[7] * rz);
}

// =============== launch ===============
// Single stream; kernel launches + one cudaFuncSetAttribute only.
// gemm_mma at launch index 3 (the slot ncu samples).
extern "C" void kernel_launch(void* const* d_in, const int* in_sizes, int n_in,
                              void* d_out, int out_size) {
    const float* x   = (const float*)d_in[0];
    const float* Wq  = (const float*)d_in[1];
    const float* Wk  = (const float*)d_in[2];
    const float* Wv  = (const float*)d_in[3];
    const int*   src = (const int*)d_in[4];
    const int*   dst = (const int*)d_in[5];
    float* out = (float*)d_out;

    cudaFuncSetAttribute(gemm_mma, cudaFuncAttributeMaxDynamicSharedMemorySize, GEMM_SMEM);

    // 0: bf16 split of x (+ zero g_deg)
    conv_x_kernel<<<(N_NODES * D_MODEL / 4 + 255) / 256, 256>>>(x);
    // 1: bf16 split of W (+ histogram of dst)
    conv_w_kernel<<<(NTOT * D_MODEL + 255) / 256, 256>>>(Wq, Wk, Wv, dst);
    // 2: per-block exclusive scan of degrees
    scan_partial<<<N_SBLK, 256>>>();
    // 3: fused QKV GEMM on tensor cores  <-- profiled launch
    dim3 ggrid((N_NODES + 127) / 128, NTOT / 128);
    gemm_mma<<<ggrid, 256, GEMM_SMEM>>>();
    // 4-6: finish binning
    scan_bsums<<<1, 256>>>();
    scan_add<<<N_SBLK, 256>>>();
    scatter_kernel<<<(N_EDGES + 255) / 256, 256>>>(src, dst);
    // 7: per-node attention + normalization
    node_attn_kernel<<<(N_NODES * 32 + 255) / 256, 256>>>(out);
}

// round 17
// speedup vs baseline: 1.2157x; 1.0143x over previous
#include <cuda_runtime.h>
#include <cuda_bf16.h>
#include <cuda_fp16.h>
#include <stdint.h>
#include <math.h>

#define N_NODES 50000
#define N_EDGES 800000
#define D_MODEL 256
#define HEADS   8
#define D_K     32
#define QKV     256
#define NTOT    768   // q|k|v concatenated

// ---------------- scratch ----------------
__device__ float g_q[N_NODES * QKV];
// k/v stored fp16 for the gather phase: per node 1024B = 512 halves
// ([0,256)=k, [256,512)=v). uint4-typed for guaranteed 16B alignment.
__device__ uint4 g_kv4[N_NODES * 64];
__device__ __nv_bfloat16 g_xhi[N_NODES * D_MODEL];
__device__ __nv_bfloat16 g_xlo[N_NODES * D_MODEL];
__device__ __nv_bfloat16 g_wthi[NTOT * D_MODEL];   // W^T rows: n in [0,768), k in [0,256)
__device__ __nv_bfloat16 g_wtlo[NTOT * D_MODEL];
__device__ int g_deg[N_NODES];
__device__ int g_off[N_NODES + 1];
__device__ int g_cur[N_NODES];
__device__ int g_srcs[N_EDGES];
#define N_SBLK ((N_NODES + 255) / 256)
__device__ int g_bsum[N_SBLK];

// ---------------- PTX helpers (plain sm_100-legal) ----------------
__device__ __forceinline__ uint32_t smem_u32(const void* p) {
    uint32_t a;
    asm("{ .reg .u64 t; cvta.to.shared.u64 t, %1; cvt.u32.u64 %0, t; }" : "=r"(a) : "l"(p));
    return a;
}
__device__ __forceinline__ void cp_async16(uint32_t daddr, const void* gptr) {
    asm volatile("cp.async.cg.shared.global [%0], [%1], 16;" :: "r"(daddr), "l"(gptr) : "memory");
}
#define CP_COMMIT() asm volatile("cp.async.commit_group;" ::: "memory")
#define CP_WAIT(n)  asm volatile("cp.async.wait_group %0;" :: "n"(n) : "memory")

__device__ __forceinline__ void ldmatrix_x4(uint32_t& a0, uint32_t& a1, uint32_t& a2, uint32_t& a3, uint32_t addr) {
    asm volatile("ldmatrix.sync.aligned.m8n8.x4.shared.b16 {%0,%1,%2,%3}, [%4];"
                 : "=r"(a0), "=r"(a1), "=r"(a2), "=r"(a3) : "r"(addr));
}
__device__ __forceinline__ void mma_bf16(float* d, const uint32_t* a, const uint32_t* b) {
    asm volatile(
        "mma.sync.aligned.m16n8k16.row.col.f32.bf16.bf16.f32 "
        "{%0,%1,%2,%3}, {%4,%5,%6,%7}, {%8,%9}, {%0,%1,%2,%3};"
        : "+f"(d[0]), "+f"(d[1]), "+f"(d[2]), "+f"(d[3])
        : "r"(a[0]), "r"(a[1]), "r"(a[2]), "r"(a[3]), "r"(b[0]), "r"(b[1]));
}

// unpack 8 fp16 (one uint4) into 8 floats
__device__ __forceinline__ void h8_to_f(const uint4& r, float* f) {
    const __half2* h = reinterpret_cast<const __half2*>(&r);
    float2 t;
    t = __half22float2(h[0]); f[0] = t.x; f[1] = t.y;
    t = __half22float2(h[1]); f[2] = t.x; f[3] = t.y;
    t = __half22float2(h[2]); f[4] = t.x; f[5] = t.y;
    t = __half22float2(h[3]); f[6] = t.x; f[7] = t.y;
}

// =============== bf16 split conversion (+ fused binning pre-work) ===============
__global__ void conv_x_kernel(const float* __restrict__ x) {
    int i = blockIdx.x * blockDim.x + threadIdx.x;   // float4 index
    if (i < N_NODES) g_deg[i] = 0;                    // fused zero of degree array
    if (i >= N_NODES * D_MODEL / 4) return;
    float4 f = *reinterpret_cast<const float4*>(x + i * 4);
    __nv_bfloat16 h[4], l[4];
    float vv[4] = {f.x, f.y, f.z, f.w};
    #pragma unroll
    for (int j = 0; j < 4; j++) {
        h[j] = __float2bfloat16_rn(vv[j]);
        l[j] = __float2bfloat16_rn(vv[j] - __bfloat162float(h[j]));
    }
    *reinterpret_cast<uint2*>(&g_xhi[i * 4]) = *reinterpret_cast<uint2*>(h);
    *reinterpret_cast<uint2*>(&g_xlo[i * 4]) = *reinterpret_cast<uint2*>(l);
}

// conv_w + fused histogram over dst
__global__ void conv_w_kernel(const float* __restrict__ Wq,
                              const float* __restrict__ Wk,
                              const float* __restrict__ Wv,
                              const int* __restrict__ dst) {
    int id = blockIdx.x * blockDim.x + threadIdx.x;  // 3*65536 = 196608 threads
    int nthreads = gridDim.x * blockDim.x;
    for (int e = id; e < N_EDGES; e += nthreads)
        atomicAdd(&g_deg[dst[e]], 1);
    if (id >= NTOT * D_MODEL) return;
    int p = id >> 16;          // proj
    int r = id & 65535;
    int k = r & 255;
    int n = r >> 8;
    const float* W = (p == 0) ? Wq : (p == 1) ? Wk : Wv;
    float v = W[k * QKV + n];
    __nv_bfloat16 h = __float2bfloat16_rn(v);
    __nv_bfloat16 l = __float2bfloat16_rn(v - __bfloat162float(h));
    g_wthi[id] = h;
    g_wtlo[id] = l;
}

// =============== mma.sync bf16 GEMM: C[50000,768] = X[50000,256] @ W[256,768] ===============
// 3 split terms folded into K loop (K_eff = 768). CTA 128x128, warp 64x32,
// BK=64. 3-stage cp.async pipeline, ONE __syncthreads per iteration (measured
// win R16). B fragments via ldmatrix_x4 (one x4 = two ni groups, halves B-load
// instruction count; bytes unchanged). __launch_bounds__(256,2): 2 CTAs/SM.
#define GEMM_STAGE_BYTES 32768          // A 16KB + B 16KB
#define GEMM_STAGES 3
#define GEMM_SMEM (GEMM_STAGES * GEMM_STAGE_BYTES)

__device__ __forceinline__ void gemm_load_stage(uint32_t sbase, int s, int it,
                                                int tileM, int nbase, int tid) {
    const int term = it >> 2;
    const int k0   = (it & 3) * 64;
    const __nv_bfloat16* __restrict__ As = (term == 1) ? g_xlo : g_xhi;
    const __nv_bfloat16* __restrict__ Bs = (term == 2) ? g_wtlo : g_wthi;
    uint32_t aBase = sbase + s * GEMM_STAGE_BYTES;
    uint32_t bBase = aBase + 16384;
    #pragma unroll
    for (int i = 0; i < 4; i++) {
        int idx = tid + i * 256;          // 0..1023
        int row = idx >> 3;
        int c   = idx & 7;
        uint32_t soff = (uint32_t)row * 128u + (uint32_t)((c ^ (row & 7)) << 4);
        int grow = tileM + row;
        if (grow >= N_NODES) grow = 0;    // garbage only pollutes invalid output rows
        cp_async16(aBase + soff, As + (size_t)grow * D_MODEL + k0 + c * 8);
        int nrow = nbase + row;
        cp_async16(bBase + soff, Bs + (size_t)nrow * D_MODEL + k0 + c * 8);
    }
}

__global__ __launch_bounds__(256, 2) void gemm_mma(void) {
    extern __shared__ char smem[];
    const uint32_t sbase = smem_u32(smem);
    const int tid  = threadIdx.x;
    const int lane = tid & 31;
    const int wid  = tid >> 5;
    const int tileM = blockIdx.x * 128;
    const int nbase = blockIdx.y * 128;
    const int wm = wid & 1;      // m sub-tile (64)
    const int wn = wid >> 1;     // n sub-tile (32)

    // hoisted ldmatrix address components
    uint32_t aRowOff[4];
    int aR7;
    {
        int arow = wm * 64 + (lane & 15);
        aR7 = arow & 7;
        #pragma unroll
        for (int mi = 0; mi < 4; mi++)
            aRowOff[mi] = (uint32_t)(arow + mi * 16) * 128u;
    }
    const int aCsel = (lane >> 4);        // 0/1
    // B x4 addressing: lane group g = lane>>3 (0..3) supplies matrix
    // (ni = 2*nip + (g>>1), k-half = g&1).
    uint32_t bRowOff[2];
    int bR7, bCsel;
    {
        int g = lane >> 3;
        int brow = wn * 32 + ((g >> 1) << 3) + (lane & 7);
        bR7 = brow & 7;                       // +16 per nip keeps &7 invariant
        bRowOff[0] = (uint32_t)brow * 128u;
        bRowOff[1] = (uint32_t)(brow + 16) * 128u;
        bCsel = g & 1;
    }

    float acc[4][4][4];
    #pragma unroll
    for (int mi = 0; mi < 4; mi++)
        #pragma unroll
        for (int ni = 0; ni < 4; ni++)
            #pragma unroll
            for (int r = 0; r < 4; r++) acc[mi][ni][r] = 0.f;

    gemm_load_stage(sbase, 0, 0, tileM, nbase, tid);
    CP_COMMIT();
    gemm_load_stage(sbase, 1, 1, tileM, nbase, tid);
    CP_COMMIT();

    int s = 0;
    for (int it = 0; it < 12; ++it) {
        if (it < 11) { CP_WAIT(1); } else { CP_WAIT(0); }
        __syncthreads();      // stage s visible; all warps done with (s+2)%3

        if (it + 2 < 12) {
            int ld = s + 2; if (ld >= GEMM_STAGES) ld -= GEMM_STAGES;
            gemm_load_stage(sbase, ld, it + 2, tileM, nbase, tid);
            CP_COMMIT();
        }

        uint32_t aBase = sbase + (uint32_t)s * GEMM_STAGE_BYTES;
        uint32_t bBase = aBase + 16384;
        #pragma unroll
        for (int k16 = 0; k16 < 4; k16++) {
            uint32_t a[4][4];
            #pragma unroll
            for (int mi = 0; mi < 4; mi++) {
                int cc = k16 * 2 + aCsel;
                uint32_t addr = aBase + aRowOff[mi] + (uint32_t)((cc ^ aR7) << 4);
                ldmatrix_x4(a[mi][0], a[mi][1], a[mi][2], a[mi][3], addr);
            }
            uint32_t b[4][2];
            #pragma unroll
            for (int nip = 0; nip < 2; nip++) {
                int cc = k16 * 2 + bCsel;
                uint32_t addr = bBase + bRowOff[nip] + (uint32_t)((cc ^ bR7) << 4);
                ldmatrix_x4(b[nip * 2][0], b[nip * 2][1],
                            b[nip * 2 + 1][0], b[nip * 2 + 1][1], addr);
            }
            #pragma unroll
            for (int mi = 0; mi < 4; mi++)
                #pragma unroll
                for (int ni = 0; ni < 4; ni++)
                    mma_bf16(acc[mi][ni], a[mi], b[ni]);
        }
        if (++s >= GEMM_STAGES) s = 0;
    }

    // epilogue: q (fp32) -> g_q; k/v (fp16 half2) -> g_kv4 region
    #pragma unroll
    for (int mi = 0; mi < 4; mi++) {
        #pragma unroll
        for (int ni = 0; ni < 4; ni++) {
            int m0 = tileM + wm * 64 + mi * 16 + (lane >> 2);
            int ng = nbase + wn * 32 + ni * 8 + (lane & 3) * 2;
            int proj = ng >> 8;
            int col  = ng & 255;
            int kvoff = (proj == 2 ? 128 : 0) + (col >> 1);   // half2 index within node
            if (m0 < N_NODES) {
                if (proj == 0) {
                    *reinterpret_cast<float2*>(g_q + (size_t)m0 * QKV + col) =
                        make_float2(acc[mi][ni][0], acc[mi][ni][1]);
                } else {
                    __half2* dstp = reinterpret_cast<__half2*>(g_kv4 + (size_t)m0 * 64) + kvoff;
                    *dstp = __floats2half2_rn(acc[mi][ni][0], acc[mi][ni][1]);
                }
            }
            if (m0 + 8 < N_NODES) {
                if (proj == 0) {
                    *reinterpret_cast<float2*>(g_q + (size_t)(m0 + 8) * QKV + col) =
                        make_float2(acc[mi][ni][2], acc[mi][ni][3]);
                } else {
                    __half2* dstp = reinterpret_cast<__half2*>(g_kv4 + (size_t)(m0 + 8) * 64) + kvoff;
                    *dstp = __floats2half2_rn(acc[mi][ni][2], acc[mi][ni][3]);
                }
            }
        }
    }
}

// =============== edge binning ===============
__global__ __launch_bounds__(256) void scan_partial() {
    __shared__ int sh[256];
    int tid = threadIdx.x;
    int i = blockIdx.x * 256 + tid;
    int v = (i < N_NODES) ? g_deg[i] : 0;
    sh[tid] = v;
    __syncthreads();
    #pragma unroll
    for (int o = 1; o < 256; o <<= 1) {
        int t = (tid >= o) ? sh[tid - o] : 0;
        __syncthreads();
        sh[tid] += t;
        __syncthreads();
    }
    if (i < N_NODES) g_off[i] = sh[tid] - v;     // exclusive within block
    if (tid == 255) g_bsum[blockIdx.x] = sh[255];
}
// fused: each block computes its own bsum prefix (N_SBLK=196 <= 256) then adds
__global__ __launch_bounds__(256) void scan_add_fused() {
    __shared__ int sh[256];
    int tid = threadIdx.x;
    int bid = blockIdx.x;
    sh[tid] = (tid < bid && tid < N_SBLK) ? g_bsum[tid] : 0;
    __syncthreads();
    #pragma unroll
    for (int o = 128; o > 0; o >>= 1) {
        if (tid < o) sh[tid] += sh[tid + o];
        __syncthreads();
    }
    int base = sh[0];
    int i = bid * 256 + tid;
    if (i < N_NODES) {
        int t = g_off[i] + base;
        g_off[i] = t;
        g_cur[i] = t;
    }
    if (bid == 0 && tid == 0) g_off[N_NODES] = N_EDGES;
}
__global__ void scatter_kernel(const int* __restrict__ src, const int* __restrict__ dst) {
    int i = blockIdx.x * blockDim.x + threadIdx.x;
    if (i < N_EDGES) {
        int p = atomicAdd(&g_cur[dst[i]], 1);
        g_srcs[p] = src[i];
    }
}

// =============== per-node attention (warp per node, fp16 k/v, depth-2 prefetch) ===============
__global__ __launch_bounds__(256) void node_attn_kernel(float* __restrict__ out) {
    const int warp = (blockIdx.x * blockDim.x + threadIdx.x) >> 5;
    const int lane = threadIdx.x & 31;
    if (warp >= N_NODES) return;
    const int n = warp;
    const int beg = g_off[n];
    const int end = g_off[n + 1];

    const float* qp = g_q + (size_t)n * QKV + lane * 8;
    const float4 q0 = *reinterpret_cast<const float4*>(qp);
    const float4 q1 = *reinterpret_cast<const float4*>(qp + 4);
    float qf[8] = {q0.x, q0.y, q0.z, q0.w, q1.x, q1.y, q1.z, q1.w};

    float af[8];
    #pragma unroll
    for (int j = 0; j < 8; j++) af[j] = 0.f;
    float z = 0.f;

    const float isd = 0.17677669529663687f;  // 1/sqrt(32)
    const unsigned FULL = 0xffffffffu;

    if (beg < end) {
        const int last = end - 1;
        // buffer 0: edge beg; buffer 1: edge beg+1 (clamped)
        const uint4* p0 = reinterpret_cast<const uint4*>(
            reinterpret_cast<const __half*>(g_kv4 + (size_t)g_srcs[beg] * 64) + lane * 8);
        int i1 = beg + 1 < end ? beg + 1 : last;
        const uint4* p1 = reinterpret_cast<const uint4*>(
            reinterpret_cast<const __half*>(g_kv4 + (size_t)g_srcs[i1] * 64) + lane * 8);
        uint4 k0r = p0[0], v0r = p0[32];
        uint4 k1r = p1[0], v1r = p1[32];

        for (int i = beg; i < end; i++) {
            int nidx = i + 2 <= last ? i + 2 : last;   // depth-2 clamped prefetch
            const uint4* np = reinterpret_cast<const uint4*>(
                reinterpret_cast<const __half*>(g_kv4 + (size_t)g_srcs[nidx] * 64) + lane * 8);
            uint4 k2r = np[0];
            uint4 v2r = np[32];

            float kf[8], vf[8];
            h8_to_f(k0r, kf);
            h8_to_f(v0r, vf);

            float p = kf[0] * qf[0];
            #pragma unroll
            for (int j = 1; j < 8; j++) p = fmaf(kf[j], qf[j], p);
            p += __shfl_xor_sync(FULL, p, 1);
            p += __shfl_xor_sync(FULL, p, 2);
            // p = full head dot, replicated on the head's 4 lanes

            float e = __expf(fminf(fmaxf(p * isd, -5.f), 5.f));
            z += e;
            #pragma unroll
            for (int j = 0; j < 8; j++) af[j] = fmaf(vf[j], e, af[j]);

            k0r = k1r; v0r = v1r;
            k1r = k2r; v1r = v2r;
        }
    }

    const float rz = 1.f / (z + 1e-9f);
    float* op = out + (size_t)n * QKV + lane * 8;
    *reinterpret_cast<float4*>(op) =
        make_float4(af[0] * rz, af[1] * rz, af[2] * rz, af[3] * rz);
    *reinterpret_cast<float4*>(op + 4) =
        make_float4(af[4] * rz, af[5] * rz, af[6] * rz, af[7] * rz);
}

// =============== launch ===============
// Single stream; kernel launches + one cudaFuncSetAttribute only.
// gemm_mma at launch index 3 (the slot ncu samples).
extern "C" void kernel_launch(void* const* d_in, const int* in_sizes, int n_in,
                              void* d_out, int out_size) {
    const float* x   = (const float*)d_in[0];
    const float* Wq  = (const float*)d_in[1];
    const float* Wk  = (const float*)d_in[2];
    const float* Wv  = (const float*)d_in[3];
    const int*   src = (const int*)d_in[4];
    const int*   dst = (const int*)d_in[5];
    float* out = (float*)d_out;

    cudaFuncSetAttribute(gemm_mma, cudaFuncAttributeMaxDynamicSharedMemorySize, GEMM_SMEM);

    // 0: bf16 split of x (+ zero g_deg)
    conv_x_kernel<<<(N_NODES * D_MODEL / 4 + 255) / 256, 256>>>(x);
    // 1: bf16 split of W (+ histogram of dst)
    conv_w_kernel<<<(NTOT * D_MODEL + 255) / 256, 256>>>(Wq, Wk, Wv, dst);
    // 2: per-block exclusive scan of degrees
    scan_partial<<<N_SBLK, 256>>>();
    // 3: fused QKV GEMM on tensor cores  <-- profiled launch
    dim3 ggrid((N_NODES + 127) / 128, NTOT / 128);
    gemm_mma<<<ggrid, 256, GEMM_SMEM>>>();
    // 4-5: finish binning (block-prefix fused into scan_add)
    scan_add_fused<<<N_SBLK, 256>>>();
    scatter_kernel<<<(N_EDGES + 255) / 256, 256>>>(src, dst);
    // 6: per-node attention + normalization
    node_attn_kernel<<<(N_NODES * 32 + 255) / 256, 256>>>(out);
}